// round 2
// baseline (speedup 1.0000x reference)
#include <cuda_runtime.h>

// ScatterLoss: loss = (||S_tot||^2 - sum_c ||S_c||^2) / (N^2 - sum_c n_c^2)
// where S_c = sum of L2-normalized rows of class c.
// One pass over e (8 MB), O(C*D) finalize. No N x N similarity matrix.

#define D_DIM 256
#define C_MAX 256   // labels are < 100; pad to 256 so finalize maps thread->class

__device__ float g_csum[C_MAX * D_DIM];   // per-class normalized-row sums
__device__ int   g_ccnt[C_MAX];           // per-class counts

// ---------------------------------------------------------------- zero scratch
__global__ void zero_k() {
    int i = blockIdx.x * blockDim.x + threadIdx.x;
    if (i < C_MAX * D_DIM) g_csum[i] = 0.0f;
    if (i < C_MAX)         g_ccnt[i] = 0;
}

// ------------------------------------------- normalize rows + scatter to class
// One warp per row. Each lane owns 8 columns (two float4s).
// NOTE: y is int32 (JAX downcasts int64 -> int32 without x64 mode).
__global__ void accum_k(const float* __restrict__ e,
                        const int* __restrict__ y,
                        int N) {
    int row  = blockIdx.x * (blockDim.x >> 5) + (threadIdx.x >> 5);
    if (row >= N) return;
    int lane = threadIdx.x & 31;

    const float4* er = (const float4*)(e + (size_t)row * D_DIM);
    float4 a = er[lane];        // cols 4*lane .. 4*lane+3
    float4 b = er[lane + 32];   // cols 128+4*lane .. 128+4*lane+3

    float s = a.x * a.x + a.y * a.y + a.z * a.z + a.w * a.w
            + b.x * b.x + b.y * b.y + b.z * b.z + b.w * b.w;
    #pragma unroll
    for (int o = 16; o > 0; o >>= 1)
        s += __shfl_xor_sync(0xffffffffu, s, o);

    float r = rsqrtf(s);

    int c = y[row];
    if ((unsigned)c >= C_MAX) return;   // defensive: never fault on bad labels

    float* dst = g_csum + c * D_DIM;
    int i0 = lane * 4;
    atomicAdd(dst + i0 + 0,       a.x * r);
    atomicAdd(dst + i0 + 1,       a.y * r);
    atomicAdd(dst + i0 + 2,       a.z * r);
    atomicAdd(dst + i0 + 3,       a.w * r);
    atomicAdd(dst + i0 + 128 + 0, b.x * r);
    atomicAdd(dst + i0 + 128 + 1, b.y * r);
    atomicAdd(dst + i0 + 128 + 2, b.z * r);
    atomicAdd(dst + i0 + 128 + 3, b.w * r);

    if (lane == 0) atomicAdd(&g_ccnt[c], 1);
}

// --------------------------------------------------------------------- finalize
// One block, 256 threads. Thread d owns column d of the class sums AND class d
// of the counts. numerator = sum_d ( (sum_c S_c[d])^2 - sum_c S_c[d]^2 ).
__global__ void fin_k(float* __restrict__ out, int N) {
    __shared__ float s_num[D_DIM];
    __shared__ float s_cnt[D_DIM];
    int d = threadIdx.x;

    float tot = 0.0f, sq = 0.0f;
    #pragma unroll 8
    for (int c = 0; c < C_MAX; c++) {
        float v = g_csum[c * D_DIM + d];   // warp reads 32 consecutive d: coalesced
        tot += v;
        sq  += v * v;
    }
    s_num[d] = tot * tot - sq;

    float cnt = (float)g_ccnt[d];
    s_cnt[d] = cnt * cnt;
    __syncthreads();

    #pragma unroll
    for (int o = 128; o > 0; o >>= 1) {
        if (d < o) {
            s_num[d] += s_num[d + o];
            s_cnt[d] += s_cnt[d + o];
        }
        __syncthreads();
    }

    if (d == 0) {
        double num = (double)s_num[0];
        double den = (double)N * (double)N - (double)s_cnt[0];
        out[0] = (float)(num / den);
    }
}

// ----------------------------------------------------------------------- launch
extern "C" void kernel_launch(void* const* d_in, const int* in_sizes, int n_in,
                              void* d_out, int out_size) {
    const float* e   = (const float*)d_in[0];
    const int*   y   = (const int*)d_in[1];
    float*       out = (float*)d_out;

    int N = in_sizes[1];                 // rows; D fixed at 256 per problem shape

    zero_k<<<(C_MAX * D_DIM + 255) / 256, 256>>>();

    int rows_per_blk = 256 / 32;         // 8 warps per block, 1 row per warp
    int nblk = (N + rows_per_blk - 1) / rows_per_blk;
    accum_k<<<nblk, 256>>>(e, y, N);

    fin_k<<<1, D_DIM>>>(out, N);
}

// round 3
// speedup vs baseline: 1.5342x; 1.5342x over previous
#include <cuda_runtime.h>

// ScatterLoss, single fused kernel:
//   loss = (||S_tot||^2 - sum_c ||S_c||^2) / (N^2 - sum_c n_c^2),
//   S_c = sum of L2-normalized rows with label c.
// Phase 1 (all blocks): stream rows, normalize, v4-red into per-class sums.
// Phase 2 (last block): finalize scalar, then re-zero scratch for next replay.

#define D_DIM 256
#define C_PAD 128      // labels are in [0,100); pad to 128
#define NBLK  296      // 2 CTAs per SM on 148-SM part
#define NTHR  256

__device__ float    g_csum[C_PAD * D_DIM];  // zero at module load; re-zeroed each run
__device__ int      g_ccnt[C_PAD];
__device__ unsigned g_done;

__device__ __forceinline__ void red_v4(float* p, float x, float y, float z, float w) {
    asm volatile("red.global.add.v4.f32 [%0], {%1, %2, %3, %4};"
                 :: "l"(p), "f"(x), "f"(y), "f"(z), "f"(w) : "memory");
}

__global__ __launch_bounds__(NTHR, 2)
void fused_k(const float* __restrict__ e, const int* __restrict__ y,
             int N, float* __restrict__ out) {
    const int lane  = threadIdx.x & 31;
    const int gwarp = (blockIdx.x * NTHR + threadIdx.x) >> 5;
    const int nwarp = (NBLK * NTHR) >> 5;

    // ---- Phase 1: one warp per row, grid-stride over rows -------------------
    for (int row = gwarp; row < N; row += nwarp) {
        const float4* er = (const float4*)(e + (size_t)row * D_DIM);
        float4 a = er[lane];        // cols 4*lane .. 4*lane+3
        float4 b = er[lane + 32];   // cols 128+4*lane ..

        float s = a.x * a.x + a.y * a.y + a.z * a.z + a.w * a.w
                + b.x * b.x + b.y * b.y + b.z * b.z + b.w * b.w;
        #pragma unroll
        for (int o = 16; o > 0; o >>= 1)
            s += __shfl_xor_sync(0xffffffffu, s, o);

        float r = rsqrtf(s);
        int   c = y[row];
        if ((unsigned)c < C_PAD) {
            float* dst = g_csum + c * D_DIM + lane * 4;
            red_v4(dst,       a.x * r, a.y * r, a.z * r, a.w * r);
            red_v4(dst + 128, b.x * r, b.y * r, b.z * r, b.w * r);
            if (lane == 0) atomicAdd(&g_ccnt[c], 1);
        }
    }

    // ---- Elect last block ---------------------------------------------------
    __shared__ unsigned s_rank;
    __threadfence();                 // make this thread's reds globally visible
    __syncthreads();                 // all threads in block fenced
    if (threadIdx.x == 0) s_rank = atomicAdd(&g_done, 1u);
    __syncthreads();
    if (s_rank != NBLK - 1) return;

    // ---- Phase 2: finalize (last block only) --------------------------------
    // thread d owns column d of the class sums and class d (d<C_PAD) of counts.
    const int d = threadIdx.x;
    float tot = 0.0f, sq = 0.0f;
    #pragma unroll 8
    for (int c = 0; c < C_PAD; c++) {
        float v = __ldcg(&g_csum[c * D_DIM + d]);   // L2 read (atomics live in L2)
        tot += v;
        sq  += v * v;
    }
    __shared__ float s_num[NTHR];
    __shared__ float s_cnt[NTHR];
    s_num[d] = tot * tot - sq;
    float cc = (d < C_PAD) ? (float)__ldcg(&g_ccnt[d]) : 0.0f;
    s_cnt[d] = cc * cc;
    __syncthreads();

    #pragma unroll
    for (int o = NTHR / 2; o > 0; o >>= 1) {
        if (d < o) {
            s_num[d] += s_num[d + o];
            s_cnt[d] += s_cnt[d + o];
        }
        __syncthreads();
    }

    if (d == 0) {
        double num = (double)s_num[0];
        double den = (double)N * (double)N - (double)s_cnt[0];
        out[0] = (float)(num / den);
    }

    // ---- Re-zero scratch so the next graph replay starts clean --------------
    float4* z = (float4*)g_csum;
    #pragma unroll 4
    for (int i = d; i < C_PAD * D_DIM / 4; i += NTHR)
        z[i] = make_float4(0.f, 0.f, 0.f, 0.f);
    if (d < C_PAD) g_ccnt[d] = 0;
    if (d == 0)    g_done = 0;
}

extern "C" void kernel_launch(void* const* d_in, const int* in_sizes, int n_in,
                              void* d_out, int out_size) {
    const float* e   = (const float*)d_in[0];
    const int*   y   = (const int*)d_in[1];
    float*       out = (float*)d_out;
    int N = in_sizes[1];

    fused_k<<<NBLK, NTHR>>>(e, y, N, out);
}

// round 4
// speedup vs baseline: 1.9106x; 1.2453x over previous
#include <cuda_runtime.h>

// ScatterLoss, single fused kernel:
//   loss = (||S_tot||^2 - sum_c ||S_c||^2) / (N^2 - sum_c n_c^2),
//   S_c = sum of L2-normalized rows with label c.
// Phase 1: 1 warp = 2 rows, all loads up-front (MLP 4), red.v4 into class table.
// Phase 2: last block finalizes with float4 L2 reads, then re-zeros scratch.

#define D_DIM 256
#define C_PAD 128      // labels in [0,100); pad to 128
#define NTHR  256      // 8 warps/CTA, 16 rows/CTA

__device__ float    g_csum[C_PAD * D_DIM];  // zero at load; re-zeroed each run
__device__ int      g_ccnt[C_PAD];
__device__ unsigned g_done;

__device__ __forceinline__ void red_v4(float* p, float x, float y, float z, float w) {
    asm volatile("red.global.add.v4.f32 [%0], {%1, %2, %3, %4};"
                 :: "l"(p), "f"(x), "f"(y), "f"(z), "f"(w) : "memory");
}

__global__ __launch_bounds__(NTHR, 4)
void fused_k(const float* __restrict__ e, const int* __restrict__ y,
             int N, float* __restrict__ out) {
    const int lane = threadIdx.x & 31;
    const int w    = (blockIdx.x * NTHR + threadIdx.x) >> 5;   // global warp id

    // ---- Phase 1: warp w handles rows 2w and 2w+1 ---------------------------
    const int r0 = 2 * w;
    const int r1 = 2 * w + 1;

    if (r0 < N) {
        const float4* e0 = (const float4*)(e + (size_t)r0 * D_DIM);
        const float4* e1 = (const float4*)(e + (size_t)r1 * D_DIM);
        const bool has1 = (r1 < N);

        // all loads issued before any dependent math (MLP = 4)
        float4 a0 = e0[lane];
        float4 b0 = e0[lane + 32];
        float4 a1, b1;
        if (has1) { a1 = e1[lane]; b1 = e1[lane + 32]; }
        else      { a1 = make_float4(0,0,0,0); b1 = a1; }

        float s0 = a0.x*a0.x + a0.y*a0.y + a0.z*a0.z + a0.w*a0.w
                 + b0.x*b0.x + b0.y*b0.y + b0.z*b0.z + b0.w*b0.w;
        float s1 = a1.x*a1.x + a1.y*a1.y + a1.z*a1.z + a1.w*a1.w
                 + b1.x*b1.x + b1.y*b1.y + b1.z*b1.z + b1.w*b1.w;
        #pragma unroll
        for (int o = 16; o > 0; o >>= 1) {   // two chains interleave in the pipe
            s0 += __shfl_xor_sync(0xffffffffu, s0, o);
            s1 += __shfl_xor_sync(0xffffffffu, s1, o);
        }
        float q0 = rsqrtf(s0);
        float q1 = rsqrtf(s1);

        int c0 = y[r0];
        int c1 = has1 ? y[r1] : -1;

        if ((unsigned)c0 < C_PAD) {
            float* d0 = g_csum + c0 * D_DIM + lane * 4;
            red_v4(d0,       a0.x*q0, a0.y*q0, a0.z*q0, a0.w*q0);
            red_v4(d0 + 128, b0.x*q0, b0.y*q0, b0.z*q0, b0.w*q0);
            if (lane == 0) atomicAdd(&g_ccnt[c0], 1);
        }
        if ((unsigned)c1 < C_PAD) {
            float* d1 = g_csum + c1 * D_DIM + lane * 4;
            red_v4(d1,       a1.x*q1, a1.y*q1, a1.z*q1, a1.w*q1);
            red_v4(d1 + 128, b1.x*q1, b1.y*q1, b1.z*q1, b1.w*q1);
            if (lane == 1) atomicAdd(&g_ccnt[c1], 1);
        }
    }

    // ---- Elect last block ---------------------------------------------------
    __shared__ unsigned s_rank;
    __threadfence();
    __syncthreads();
    if (threadIdx.x == 0) s_rank = atomicAdd(&g_done, 1u);
    __syncthreads();
    if (s_rank != gridDim.x - 1) return;

    // ---- Phase 2: finalize (last block only) --------------------------------
    // 4 class-groups x 64 column-threads; float4 reads for MLP.
    const int tid = threadIdx.x;
    const int t   = tid & 63;          // column group: cols 4t..4t+3
    const int g   = tid >> 6;          // class group: classes g, g+4, ...

    const float4* csum4 = (const float4*)g_csum;
    float4 tot = make_float4(0,0,0,0);
    float  sqs = 0.0f;
    #pragma unroll 8
    for (int c = g; c < C_PAD; c += 4) {
        float4 v = __ldcg(&csum4[c * 64 + t]);
        tot.x += v.x; tot.y += v.y; tot.z += v.z; tot.w += v.w;
        sqs   += v.x*v.x + v.y*v.y + v.z*v.z + v.w*v.w;
    }

    __shared__ float4 s_tot[4][64];
    __shared__ float  s_red[NTHR];
    s_tot[g][t] = tot;

    float cc = (tid < C_PAD) ? (float)__ldcg(&g_ccnt[tid]) : 0.0f;
    s_red[tid] = -sqs;                 // numerator gets -sum_c ||S_c||^2
    __syncthreads();

    // 64 threads: full column totals -> + (sum_c S_c[d])^2
    if (tid < 64) {
        float4 T;
        T.x = s_tot[0][tid].x + s_tot[1][tid].x + s_tot[2][tid].x + s_tot[3][tid].x;
        T.y = s_tot[0][tid].y + s_tot[1][tid].y + s_tot[2][tid].y + s_tot[3][tid].y;
        T.z = s_tot[0][tid].z + s_tot[1][tid].z + s_tot[2][tid].z + s_tot[3][tid].z;
        T.w = s_tot[0][tid].w + s_tot[1][tid].w + s_tot[2][tid].w + s_tot[3][tid].w;
        s_red[tid] += T.x*T.x + T.y*T.y + T.z*T.z + T.w*T.w;
    }
    __shared__ float s_cnt[NTHR];
    s_cnt[tid] = cc * cc;
    __syncthreads();

    #pragma unroll
    for (int o = NTHR / 2; o > 0; o >>= 1) {
        if (tid < o) {
            s_red[tid] += s_red[tid + o];
            s_cnt[tid] += s_cnt[tid + o];
        }
        __syncthreads();
    }

    if (tid == 0) {
        double num = (double)s_red[0];
        double den = (double)N * (double)N - (double)s_cnt[0];
        out[0] = (float)(num / den);
    }

    // ---- Re-zero scratch for the next graph replay --------------------------
    float4* z = (float4*)g_csum;
    #pragma unroll 4
    for (int i = tid; i < C_PAD * D_DIM / 4; i += NTHR)
        z[i] = make_float4(0.f, 0.f, 0.f, 0.f);
    if (tid < C_PAD) g_ccnt[tid] = 0;
    if (tid == 0)    g_done = 0;
}

extern "C" void kernel_launch(void* const* d_in, const int* in_sizes, int n_in,
                              void* d_out, int out_size) {
    const float* e   = (const float*)d_in[0];
    const int*   y   = (const int*)d_in[1];
    float*       out = (float*)d_out;
    int N = in_sizes[1];

    int rows_per_blk = (NTHR / 32) * 2;               // 16
    int nblk = (N + rows_per_blk - 1) / rows_per_blk; // 512 for N=8192
    fused_k<<<nblk, NTHR>>>(e, y, N, out);
}